// round 10
// baseline (speedup 1.0000x reference)
#include <cuda_runtime.h>
#include <math.h>

// ---------------- problem constants ----------------
#define B_   2
#define S_   2048
#define D_   4096
#define H_   32
#define KV_  8
#define HD_  128
#define T_   (B_ * S_)                 // 4096 tokens
#define NQKV_ ((H_ + 2 * KV_) * HD_)   // 6144
#define SCALE_ 0.08838834764831845f    // 1/sqrt(128)

// ---------------- device scratch (static globals: alloc-free rule) ----------------
__device__ float g_qkv[(size_t)T_ * NQKV_];            // [T, 6144]
__device__ float g_q  [(size_t)B_ * H_  * S_ * HD_];   // [B,H,S,HD]
__device__ float g_k  [(size_t)B_ * KV_ * S_ * HD_];   // [B,KV,S,HD]
__device__ float g_v  [(size_t)B_ * KV_ * S_ * HD_];   // [B,KV,S,HD]
__device__ float g_attn[(size_t)T_ * (H_ * HD_)];      // [T, 4096] = [B,S,H*HD]
__device__ float g_cos[S_ * (HD_ / 2)];
__device__ float g_sin[S_ * (HD_ / 2)];

// ---------------- 1) RoPE cos/sin table (fp64 for angle precision) ----------------
__global__ void rope_table_kernel() {
    int idx = blockIdx.x * blockDim.x + threadIdx.x;
    if (idx >= S_ * 64) return;
    int p = idx >> 6;
    int i = idx & 63;
    double inv_freq = pow(10000.0, -(2.0 * (double)i) / 128.0);
    double ang = (double)p * inv_freq;
    g_cos[idx] = (float)cos(ang);
    g_sin[idx] = (float)sin(ang);
}

// ---------------- 2) fp32 GEMM: C[M,N] = A[M,K] @ B[K,N], all row-major ----------------
// 128x128 block tile, BK=16, 256 threads, 8x8 per-thread register tile.
__global__ __launch_bounds__(256) void gemm128_kernel(
    const float* __restrict__ A, const float* __restrict__ Bm,
    float* __restrict__ C, int M, int N, int K)
{
    __shared__ float As[16 * 132];   // transposed: As[k][m], padded stride 132
    __shared__ float Bs[16 * 128];   // natural:    Bs[k][n]

    const int tid = threadIdx.x;
    const int tx = tid & 15;
    const int ty = tid >> 4;
    const int m0 = blockIdx.y * 128;
    const int n0 = blockIdx.x * 128;

    float acc[8][8];
#pragma unroll
    for (int i = 0; i < 8; i++)
#pragma unroll
        for (int j = 0; j < 8; j++) acc[i][j] = 0.0f;

    for (int k0 = 0; k0 < K; k0 += 16) {
        // load A tile 128x16 (transposed into As)
#pragma unroll
        for (int li = 0; li < 2; li++) {
            int idx = tid + li * 256;          // 0..511
            int row = idx >> 2;                // 0..127
            int kc  = (idx & 3) * 4;           // 0,4,8,12
            float4 a = *(const float4*)(A + (size_t)(m0 + row) * K + k0 + kc);
            As[(kc + 0) * 132 + row] = a.x;
            As[(kc + 1) * 132 + row] = a.y;
            As[(kc + 2) * 132 + row] = a.z;
            As[(kc + 3) * 132 + row] = a.w;
        }
        // load B tile 16x128 (natural)
#pragma unroll
        for (int li = 0; li < 2; li++) {
            int idx = tid + li * 256;          // 0..511
            int kr = idx >> 5;                 // 0..15
            int n4 = (idx & 31) * 4;           // 0..124
            *(float4*)(Bs + kr * 128 + n4) =
                *(const float4*)(Bm + (size_t)(k0 + kr) * N + n0 + n4);
        }
        __syncthreads();

#pragma unroll
        for (int kk = 0; kk < 16; kk++) {
            float a[8], b[8];
            *(float4*)&a[0] = *(const float4*)(As + kk * 132 + ty * 8);
            *(float4*)&a[4] = *(const float4*)(As + kk * 132 + ty * 8 + 4);
            *(float4*)&b[0] = *(const float4*)(Bs + kk * 128 + tx * 8);
            *(float4*)&b[4] = *(const float4*)(Bs + kk * 128 + tx * 8 + 4);
#pragma unroll
            for (int i = 0; i < 8; i++)
#pragma unroll
                for (int j = 0; j < 8; j++)
                    acc[i][j] += a[i] * b[j];
        }
        __syncthreads();
    }

#pragma unroll
    for (int i = 0; i < 8; i++) {
        float* cp = C + (size_t)(m0 + ty * 8 + i) * N + n0 + tx * 8;
        *(float4*)(cp + 0) = make_float4(acc[i][0], acc[i][1], acc[i][2], acc[i][3]);
        *(float4*)(cp + 4) = make_float4(acc[i][4], acc[i][5], acc[i][6], acc[i][7]);
    }
}

// ---------------- 3) fused per-head RMSNorm + RoPE + scatter to [B,head,S,HD] ----------------
__global__ __launch_bounds__(256) void normrope_kernel(
    const float* __restrict__ q_norm_w, const float* __restrict__ k_norm_w,
    const int* __restrict__ positions)
{
    const int t    = blockIdx.x;            // token 0..4095
    const int lane = threadIdx.x & 31;
    const int warp = threadIdx.x >> 5;      // 0..7
    const int b = t >> 11;                  // t / 2048
    const int s = t & 2047;

    int p = positions[t];
    if (p < 0) p = 0;
    if (p >= S_) p = S_ - 1;

    const float* row = g_qkv + (size_t)t * NQKV_;

    for (int h = warp; h < (H_ + 2 * KV_); h += 8) {   // 48 heads: 32 q, 8 k, 8 v
        const float* x = row + h * HD_;
        float x0 = x[lane];
        float x1 = x[lane + 32];
        float x2 = x[lane + 64];
        float x3 = x[lane + 96];

        if (h < H_ + KV_) {
            // q or k head: RMSNorm then RoPE
            float ss = x0 * x0 + x1 * x1 + x2 * x2 + x3 * x3;
#pragma unroll
            for (int off = 16; off >= 1; off >>= 1)
                ss += __shfl_xor_sync(0xffffffffu, ss, off);
            float r = rsqrtf(ss * (1.0f / 128.0f) + 1e-6f);

            const float* w = (h < H_) ? q_norm_w : k_norm_w;
            float y0 = x0 * r * w[lane];
            float y1 = x1 * r * w[lane + 32];
            float y2 = x2 * r * w[lane + 64];
            float y3 = x3 * r * w[lane + 96];

            float ca = g_cos[p * 64 + lane];
            float cb = g_cos[p * 64 + lane + 32];
            float sa = g_sin[p * 64 + lane];
            float sb = g_sin[p * 64 + lane + 32];

            float o0 = y0 * ca - y2 * sa;       // first half
            float o1 = y1 * cb - y3 * sb;
            float o2 = y2 * ca + y0 * sa;       // second half
            float o3 = y3 * cb + y1 * sb;

            float* dst;
            if (h < H_)
                dst = g_q + (((size_t)(b * H_ + h) * S_ + s) * HD_);
            else
                dst = g_k + (((size_t)(b * KV_ + (h - H_)) * S_ + s) * HD_);
            dst[lane]      = o0;
            dst[lane + 32] = o1;
            dst[lane + 64] = o2;
            dst[lane + 96] = o3;
        } else {
            // v head: plain copy
            float* dst = g_v + (((size_t)(b * KV_ + (h - H_ - KV_)) * S_ + s) * HD_);
            dst[lane]      = x0;
            dst[lane + 32] = x1;
            dst[lane + 64] = x2;
            dst[lane + 96] = x3;
        }
    }
}

// ---------------- 4) flash attention (causal GQA), fp32, online softmax ----------------
// Block: 256 threads (16x16). Q tile 64 rows, KV tile 64 cols.
// Dynamic smem: Qs[128][64] + Ks[128][64] (d-major) + Vs[64][128] + Ps[64][64]
#define ATT_SMEM_FLOATS (128 * 64 + 128 * 64 + 64 * 128 + 64 * 64)  // 28672
#define ATT_SMEM_BYTES  (ATT_SMEM_FLOATS * 4)                       // 114688

__global__ __launch_bounds__(256) void attention_kernel() {
    extern __shared__ float sm[];
    float* Qs = sm;                       // [d][r]  d-major, 128x64
    float* Ks = Qs + 128 * 64;            // [d][c]  d-major, 128x64
    float* Vs = Ks + 128 * 64;            // [r][d]  natural, 64x128
    float* Ps = Vs + 64 * 128;            // [r][c]  64x64

    const int q0 = blockIdx.x;            // q tile 0..31
    const int h  = blockIdx.y;            // head 0..31
    const int b  = blockIdx.z;            // batch 0..1
    const int kh = h >> 2;                // GQA: kv head = h / 4

    const int tid = threadIdx.x;
    const int tx = tid & 15;
    const int ty = tid >> 4;

    const float* Q = g_q + ((size_t)(b * H_ + h) * S_ + q0 * 64) * HD_;
    const float* K = g_k + ((size_t)(b * KV_ + kh) * S_) * HD_;
    const float* V = g_v + ((size_t)(b * KV_ + kh) * S_) * HD_;

    // load Q tile transposed into Qs[d][r]
    for (int idx = tid; idx < 64 * 32; idx += 256) {
        int d4 = idx >> 6;                 // 0..31
        int r  = idx & 63;
        float4 q = *(const float4*)(Q + (size_t)r * HD_ + d4 * 4);
        Qs[(d4 * 4 + 0) * 64 + r] = q.x;
        Qs[(d4 * 4 + 1) * 64 + r] = q.y;
        Qs[(d4 * 4 + 2) * 64 + r] = q.z;
        Qs[(d4 * 4 + 3) * 64 + r] = q.w;
    }

    float m[4], l[4], o[4][8];
#pragma unroll
    for (int i = 0; i < 4; i++) {
        m[i] = -1e30f;
        l[i] = 0.0f;
#pragma unroll
        for (int j = 0; j < 8; j++) o[i][j] = 0.0f;
    }

    for (int j0 = 0; j0 <= q0; j0++) {
        __syncthreads();   // prior PV done reading Vs/Ps; Qs visible after next sync too

        // load K tile transposed into Ks[d][c]
        const float* Kt = K + (size_t)j0 * 64 * HD_;
        for (int idx = tid; idx < 64 * 32; idx += 256) {
            int d4 = idx >> 6;
            int c  = idx & 63;
            float4 k = *(const float4*)(Kt + (size_t)c * HD_ + d4 * 4);
            Ks[(d4 * 4 + 0) * 64 + c] = k.x;
            Ks[(d4 * 4 + 1) * 64 + c] = k.y;
            Ks[(d4 * 4 + 2) * 64 + c] = k.z;
            Ks[(d4 * 4 + 3) * 64 + c] = k.w;
        }
        // load V tile natural into Vs[r][d]
        const float* Vt = V + (size_t)j0 * 64 * HD_;
        for (int idx = tid; idx < 64 * 32; idx += 256) {
            int r  = idx >> 5;
            int d4 = (idx & 31) * 4;
            *(float4*)(Vs + r * 128 + d4) = *(const float4*)(Vt + (size_t)r * HD_ + d4);
        }
        __syncthreads();

        // ---- QK^T: s[4][4] per thread ----
        float sacc[4][4];
#pragma unroll
        for (int i = 0; i < 4; i++)
#pragma unroll
            for (int j = 0; j < 4; j++) sacc[i][j] = 0.0f;

#pragma unroll 4
        for (int d = 0; d < 128; d++) {
            float4 qv = *(const float4*)(Qs + d * 64 + ty * 4);
            float4 kv = *(const float4*)(Ks + d * 64 + tx * 4);
            float qa[4] = {qv.x, qv.y, qv.z, qv.w};
            float ka[4] = {kv.x, kv.y, kv.z, kv.w};
#pragma unroll
            for (int i = 0; i < 4; i++)
#pragma unroll
                for (int j = 0; j < 4; j++)
                    sacc[i][j] += qa[i] * ka[j];
        }

#pragma unroll
        for (int i = 0; i < 4; i++)
#pragma unroll
            for (int j = 0; j < 4; j++) sacc[i][j] *= SCALE_;

        if (j0 == q0) {   // causal mask on the diagonal tile
#pragma unroll
            for (int i = 0; i < 4; i++)
#pragma unroll
                for (int j = 0; j < 4; j++)
                    if (tx * 4 + j > ty * 4 + i) sacc[i][j] = -1e30f;
        }

        // ---- online softmax ----
#pragma unroll
        for (int i = 0; i < 4; i++) {
            float rm = fmaxf(fmaxf(sacc[i][0], sacc[i][1]),
                             fmaxf(sacc[i][2], sacc[i][3]));
#pragma unroll
            for (int off = 8; off >= 1; off >>= 1)
                rm = fmaxf(rm, __shfl_xor_sync(0xffffffffu, rm, off));
            float mn   = fmaxf(m[i], rm);
            float corr = __expf(m[i] - mn);
            float p0 = __expf(sacc[i][0] - mn);
            float p1 = __expf(sacc[i][1] - mn);
            float p2 = __expf(sacc[i][2] - mn);
            float p3 = __expf(sacc[i][3] - mn);
            float rs = p0 + p1 + p2 + p3;
#pragma unroll
            for (int off = 8; off >= 1; off >>= 1)
                rs += __shfl_xor_sync(0xffffffffu, rs, off);
            l[i] = l[i] * corr + rs;
            m[i] = mn;
#pragma unroll
            for (int j = 0; j < 8; j++) o[i][j] *= corr;
            *(float4*)(Ps + (ty * 4 + i) * 64 + tx * 4) = make_float4(p0, p1, p2, p3);
        }
        __syncthreads();

        // ---- P @ V: accumulate into o[4][8] ----
#pragma unroll 2
        for (int jj = 0; jj < 64; jj++) {
            float pr[4];
#pragma unroll
            for (int i = 0; i < 4; i++) pr[i] = Ps[(ty * 4 + i) * 64 + jj];
            float4 v0 = *(const float4*)(Vs + jj * 128 + tx * 8);
            float4 v1 = *(const float4*)(Vs + jj * 128 + tx * 8 + 4);
            float va[8] = {v0.x, v0.y, v0.z, v0.w, v1.x, v1.y, v1.z, v1.w};
#pragma unroll
            for (int i = 0; i < 4; i++)
#pragma unroll
                for (int j = 0; j < 8; j++)
                    o[i][j] += pr[i] * va[j];
        }
    }

    // epilogue: normalize and write [B,S,H*HD]
#pragma unroll
    for (int i = 0; i < 4; i++) {
        float inv = 1.0f / l[i];
        int r = q0 * 64 + ty * 4 + i;
        float* dst = g_attn + ((size_t)(b * S_ + r) * H_ + h) * HD_ + tx * 8;
        *(float4*)(dst + 0) = make_float4(o[i][0] * inv, o[i][1] * inv,
                                          o[i][2] * inv, o[i][3] * inv);
        *(float4*)(dst + 4) = make_float4(o[i][4] * inv, o[i][5] * inv,
                                          o[i][6] * inv, o[i][7] * inv);
    }
}

// ---------------- host launcher ----------------
extern "C" void kernel_launch(void* const* d_in, const int* in_sizes, int n_in,
                              void* d_out, int out_size) {
    const int*   positions = (const int*)  d_in[0];
    const float* hidden    = (const float*)d_in[1];
    const float* w_qkv     = (const float*)d_in[2];
    const float* w_o       = (const float*)d_in[3];
    const float* q_norm_w  = (const float*)d_in[4];
    const float* k_norm_w  = (const float*)d_in[5];
    float*       out       = (float*)d_out;

    float *qkv_ptr, *attn_ptr;
    cudaGetSymbolAddress((void**)&qkv_ptr,  g_qkv);
    cudaGetSymbolAddress((void**)&attn_ptr, g_attn);

    cudaFuncSetAttribute(attention_kernel,
                         cudaFuncAttributeMaxDynamicSharedMemorySize, ATT_SMEM_BYTES);

    // 1) RoPE tables (independent)
    rope_table_kernel<<<(S_ * 64 + 255) / 256, 256>>>();

    // 2) QKV projection: [4096,4096] @ [4096,6144]
    gemm128_kernel<<<dim3(NQKV_ / 128, T_ / 128), 256>>>(
        hidden, w_qkv, qkv_ptr, T_, NQKV_, D_);

    // 3) RMSNorm + RoPE + layout
    normrope_kernel<<<T_, 256>>>(q_norm_w, k_norm_w, positions);

    // 4) causal GQA flash attention
    attention_kernel<<<dim3(S_ / 64, H_, B_), 256, ATT_SMEM_BYTES>>>();

    // 5) output projection: [4096,4096] @ [4096,4096] -> d_out
    gemm128_kernel<<<dim3(D_ / 128, T_ / 128), 256>>>(
        attn_ptr, w_o, out, T_, D_, H_ * HD_);
}

// round 11
// speedup vs baseline: 1.0022x; 1.0022x over previous
#include <cuda_runtime.h>
#include <math.h>

// ---------------- problem constants ----------------
#define B_   2
#define S_   2048
#define D_   4096
#define H_   32
#define KV_  8
#define HD_  128
#define T_   (B_ * S_)                 // 4096 tokens
#define NQKV_ ((H_ + 2 * KV_) * HD_)   // 6144
#define SCALE_ 0.08838834764831845f    // 1/sqrt(128)

// ---------------- device scratch (static globals: alloc-free rule) ----------------
__device__ float g_qkv[(size_t)T_ * NQKV_];            // [T, 6144]
__device__ float g_q  [(size_t)B_ * H_  * S_ * HD_];   // [B,H,S,HD]
__device__ float g_k  [(size_t)B_ * KV_ * S_ * HD_];   // [B,KV,S,HD]
__device__ float g_v  [(size_t)B_ * KV_ * S_ * HD_];   // [B,KV,S,HD]
__device__ float g_attn[(size_t)T_ * (H_ * HD_)];      // [T, 4096] = [B,S,H*HD]
__device__ float g_cos[S_ * (HD_ / 2)];
__device__ float g_sin[S_ * (HD_ / 2)];

// ---------------- 1) RoPE cos/sin table (fp64 for angle precision) ----------------
__global__ void rope_table_kernel() {
    int idx = blockIdx.x * blockDim.x + threadIdx.x;
    if (idx >= S_ * 64) return;
    int p = idx >> 6;
    int i = idx & 63;
    double inv_freq = pow(10000.0, -(2.0 * (double)i) / 128.0);
    double ang = (double)p * inv_freq;
    g_cos[idx] = (float)cos(ang);
    g_sin[idx] = (float)sin(ang);
}

// ---------------- 2) fp32 GEMM: C[M,N] = A[M,K] @ B[K,N], all row-major ----------------
// 128x128 block tile, BK=16, 256 threads, 8x8 per-thread register tile.
__global__ __launch_bounds__(256) void gemm128_kernel(
    const float* __restrict__ A, const float* __restrict__ Bm,
    float* __restrict__ C, int M, int N, int K)
{
    __shared__ float As[16 * 132];   // transposed: As[k][m], padded stride 132
    __shared__ float Bs[16 * 128];   // natural:    Bs[k][n]

    const int tid = threadIdx.x;
    const int tx = tid & 15;
    const int ty = tid >> 4;
    const int m0 = blockIdx.y * 128;
    const int n0 = blockIdx.x * 128;

    float acc[8][8];
#pragma unroll
    for (int i = 0; i < 8; i++)
#pragma unroll
        for (int j = 0; j < 8; j++) acc[i][j] = 0.0f;

    for (int k0 = 0; k0 < K; k0 += 16) {
        // load A tile 128x16 (transposed into As)
#pragma unroll
        for (int li = 0; li < 2; li++) {
            int idx = tid + li * 256;          // 0..511
            int row = idx >> 2;                // 0..127
            int kc  = (idx & 3) * 4;           // 0,4,8,12
            float4 a = *(const float4*)(A + (size_t)(m0 + row) * K + k0 + kc);
            As[(kc + 0) * 132 + row] = a.x;
            As[(kc + 1) * 132 + row] = a.y;
            As[(kc + 2) * 132 + row] = a.z;
            As[(kc + 3) * 132 + row] = a.w;
        }
        // load B tile 16x128 (natural)
#pragma unroll
        for (int li = 0; li < 2; li++) {
            int idx = tid + li * 256;          // 0..511
            int kr = idx >> 5;                 // 0..15
            int n4 = (idx & 31) * 4;           // 0..124
            *(float4*)(Bs + kr * 128 + n4) =
                *(const float4*)(Bm + (size_t)(k0 + kr) * N + n0 + n4);
        }
        __syncthreads();

#pragma unroll
        for (int kk = 0; kk < 16; kk++) {
            float a[8], b[8];
            *(float4*)&a[0] = *(const float4*)(As + kk * 132 + ty * 8);
            *(float4*)&a[4] = *(const float4*)(As + kk * 132 + ty * 8 + 4);
            *(float4*)&b[0] = *(const float4*)(Bs + kk * 128 + tx * 8);
            *(float4*)&b[4] = *(const float4*)(Bs + kk * 128 + tx * 8 + 4);
#pragma unroll
            for (int i = 0; i < 8; i++)
#pragma unroll
                for (int j = 0; j < 8; j++)
                    acc[i][j] += a[i] * b[j];
        }
        __syncthreads();
    }

#pragma unroll
    for (int i = 0; i < 8; i++) {
        float* cp = C + (size_t)(m0 + ty * 8 + i) * N + n0 + tx * 8;
        *(float4*)(cp + 0) = make_float4(acc[i][0], acc[i][1], acc[i][2], acc[i][3]);
        *(float4*)(cp + 4) = make_float4(acc[i][4], acc[i][5], acc[i][6], acc[i][7]);
    }
}

// ---------------- 3) fused per-head RMSNorm + RoPE + scatter to [B,head,S,HD] ----------------
__global__ __launch_bounds__(256) void normrope_kernel(
    const float* __restrict__ q_norm_w, const float* __restrict__ k_norm_w,
    const int* __restrict__ positions)
{
    const int t    = blockIdx.x;            // token 0..4095
    const int lane = threadIdx.x & 31;
    const int warp = threadIdx.x >> 5;      // 0..7
    const int b = t >> 11;                  // t / 2048
    const int s = t & 2047;

    int p = positions[t];
    if (p < 0) p = 0;
    if (p >= S_) p = S_ - 1;

    const float* row = g_qkv + (size_t)t * NQKV_;

    for (int h = warp; h < (H_ + 2 * KV_); h += 8) {   // 48 heads: 32 q, 8 k, 8 v
        const float* x = row + h * HD_;
        float x0 = x[lane];
        float x1 = x[lane + 32];
        float x2 = x[lane + 64];
        float x3 = x[lane + 96];

        if (h < H_ + KV_) {
            // q or k head: RMSNorm then RoPE
            float ss = x0 * x0 + x1 * x1 + x2 * x2 + x3 * x3;
#pragma unroll
            for (int off = 16; off >= 1; off >>= 1)
                ss += __shfl_xor_sync(0xffffffffu, ss, off);
            float r = rsqrtf(ss * (1.0f / 128.0f) + 1e-6f);

            const float* w = (h < H_) ? q_norm_w : k_norm_w;
            float y0 = x0 * r * w[lane];
            float y1 = x1 * r * w[lane + 32];
            float y2 = x2 * r * w[lane + 64];
            float y3 = x3 * r * w[lane + 96];

            float ca = g_cos[p * 64 + lane];
            float cb = g_cos[p * 64 + lane + 32];
            float sa = g_sin[p * 64 + lane];
            float sb = g_sin[p * 64 + lane + 32];

            float o0 = y0 * ca - y2 * sa;       // first half
            float o1 = y1 * cb - y3 * sb;
            float o2 = y2 * ca + y0 * sa;       // second half
            float o3 = y3 * cb + y1 * sb;

            float* dst;
            if (h < H_)
                dst = g_q + (((size_t)(b * H_ + h) * S_ + s) * HD_);
            else
                dst = g_k + (((size_t)(b * KV_ + (h - H_)) * S_ + s) * HD_);
            dst[lane]      = o0;
            dst[lane + 32] = o1;
            dst[lane + 64] = o2;
            dst[lane + 96] = o3;
        } else {
            // v head: plain copy
            float* dst = g_v + (((size_t)(b * KV_ + (h - H_ - KV_)) * S_ + s) * HD_);
            dst[lane]      = x0;
            dst[lane + 32] = x1;
            dst[lane + 64] = x2;
            dst[lane + 96] = x3;
        }
    }
}

// ---------------- 4) flash attention (causal GQA), fp32, online softmax ----------------
// Block: 256 threads (16x16). Q tile 64 rows, KV tile 64 cols.
// Dynamic smem: Qs[128][64] + Ks[128][64] (d-major) + Vs[64][128] + Ps[64][64]
#define ATT_SMEM_FLOATS (128 * 64 + 128 * 64 + 64 * 128 + 64 * 64)  // 28672
#define ATT_SMEM_BYTES  (ATT_SMEM_FLOATS * 4)                       // 114688

__global__ __launch_bounds__(256) void attention_kernel() {
    extern __shared__ float sm[];
    float* Qs = sm;                       // [d][r]  d-major, 128x64
    float* Ks = Qs + 128 * 64;            // [d][c]  d-major, 128x64
    float* Vs = Ks + 128 * 64;            // [r][d]  natural, 64x128
    float* Ps = Vs + 64 * 128;            // [r][c]  64x64

    const int q0 = blockIdx.x;            // q tile 0..31
    const int h  = blockIdx.y;            // head 0..31
    const int b  = blockIdx.z;            // batch 0..1
    const int kh = h >> 2;                // GQA: kv head = h / 4

    const int tid = threadIdx.x;
    const int tx = tid & 15;
    const int ty = tid >> 4;

    const float* Q = g_q + ((size_t)(b * H_ + h) * S_ + q0 * 64) * HD_;
    const float* K = g_k + ((size_t)(b * KV_ + kh) * S_) * HD_;
    const float* V = g_v + ((size_t)(b * KV_ + kh) * S_) * HD_;

    // load Q tile transposed into Qs[d][r]
    for (int idx = tid; idx < 64 * 32; idx += 256) {
        int d4 = idx >> 6;                 // 0..31
        int r  = idx & 63;
        float4 q = *(const float4*)(Q + (size_t)r * HD_ + d4 * 4);
        Qs[(d4 * 4 + 0) * 64 + r] = q.x;
        Qs[(d4 * 4 + 1) * 64 + r] = q.y;
        Qs[(d4 * 4 + 2) * 64 + r] = q.z;
        Qs[(d4 * 4 + 3) * 64 + r] = q.w;
    }

    float m[4], l[4], o[4][8];
#pragma unroll
    for (int i = 0; i < 4; i++) {
        m[i] = -1e30f;
        l[i] = 0.0f;
#pragma unroll
        for (int j = 0; j < 8; j++) o[i][j] = 0.0f;
    }

    for (int j0 = 0; j0 <= q0; j0++) {
        __syncthreads();   // prior PV done reading Vs/Ps; Qs visible after next sync too

        // load K tile transposed into Ks[d][c]
        const float* Kt = K + (size_t)j0 * 64 * HD_;
        for (int idx = tid; idx < 64 * 32; idx += 256) {
            int d4 = idx >> 6;
            int c  = idx & 63;
            float4 k = *(const float4*)(Kt + (size_t)c * HD_ + d4 * 4);
            Ks[(d4 * 4 + 0) * 64 + c] = k.x;
            Ks[(d4 * 4 + 1) * 64 + c] = k.y;
            Ks[(d4 * 4 + 2) * 64 + c] = k.z;
            Ks[(d4 * 4 + 3) * 64 + c] = k.w;
        }
        // load V tile natural into Vs[r][d]
        const float* Vt = V + (size_t)j0 * 64 * HD_;
        for (int idx = tid; idx < 64 * 32; idx += 256) {
            int r  = idx >> 5;
            int d4 = (idx & 31) * 4;
            *(float4*)(Vs + r * 128 + d4) = *(const float4*)(Vt + (size_t)r * HD_ + d4);
        }
        __syncthreads();

        // ---- QK^T: s[4][4] per thread ----
        float sacc[4][4];
#pragma unroll
        for (int i = 0; i < 4; i++)
#pragma unroll
            for (int j = 0; j < 4; j++) sacc[i][j] = 0.0f;

#pragma unroll 4
        for (int d = 0; d < 128; d++) {
            float4 qv = *(const float4*)(Qs + d * 64 + ty * 4);
            float4 kv = *(const float4*)(Ks + d * 64 + tx * 4);
            float qa[4] = {qv.x, qv.y, qv.z, qv.w};
            float ka[4] = {kv.x, kv.y, kv.z, kv.w};
#pragma unroll
            for (int i = 0; i < 4; i++)
#pragma unroll
                for (int j = 0; j < 4; j++)
                    sacc[i][j] += qa[i] * ka[j];
        }

#pragma unroll
        for (int i = 0; i < 4; i++)
#pragma unroll
            for (int j = 0; j < 4; j++) sacc[i][j] *= SCALE_;

        if (j0 == q0) {   // causal mask on the diagonal tile
#pragma unroll
            for (int i = 0; i < 4; i++)
#pragma unroll
                for (int j = 0; j < 4; j++)
                    if (tx * 4 + j > ty * 4 + i) sacc[i][j] = -1e30f;
        }

        // ---- online softmax ----
#pragma unroll
        for (int i = 0; i < 4; i++) {
            float rm = fmaxf(fmaxf(sacc[i][0], sacc[i][1]),
                             fmaxf(sacc[i][2], sacc[i][3]));
#pragma unroll
            for (int off = 8; off >= 1; off >>= 1)
                rm = fmaxf(rm, __shfl_xor_sync(0xffffffffu, rm, off));
            float mn   = fmaxf(m[i], rm);
            float corr = __expf(m[i] - mn);
            float p0 = __expf(sacc[i][0] - mn);
            float p1 = __expf(sacc[i][1] - mn);
            float p2 = __expf(sacc[i][2] - mn);
            float p3 = __expf(sacc[i][3] - mn);
            float rs = p0 + p1 + p2 + p3;
#pragma unroll
            for (int off = 8; off >= 1; off >>= 1)
                rs += __shfl_xor_sync(0xffffffffu, rs, off);
            l[i] = l[i] * corr + rs;
            m[i] = mn;
#pragma unroll
            for (int j = 0; j < 8; j++) o[i][j] *= corr;
            *(float4*)(Ps + (ty * 4 + i) * 64 + tx * 4) = make_float4(p0, p1, p2, p3);
        }
        __syncthreads();

        // ---- P @ V: accumulate into o[4][8] ----
#pragma unroll 2
        for (int jj = 0; jj < 64; jj++) {
            float pr[4];
#pragma unroll
            for (int i = 0; i < 4; i++) pr[i] = Ps[(ty * 4 + i) * 64 + jj];
            float4 v0 = *(const float4*)(Vs + jj * 128 + tx * 8);
            float4 v1 = *(const float4*)(Vs + jj * 128 + tx * 8 + 4);
            float va[8] = {v0.x, v0.y, v0.z, v0.w, v1.x, v1.y, v1.z, v1.w};
#pragma unroll
            for (int i = 0; i < 4; i++)
#pragma unroll
                for (int j = 0; j < 8; j++)
                    o[i][j] += pr[i] * va[j];
        }
    }

    // epilogue: normalize and write [B,S,H*HD]
#pragma unroll
    for (int i = 0; i < 4; i++) {
        float inv = 1.0f / l[i];
        int r = q0 * 64 + ty * 4 + i;
        float* dst = g_attn + ((size_t)(b * S_ + r) * H_ + h) * HD_ + tx * 8;
        *(float4*)(dst + 0) = make_float4(o[i][0] * inv, o[i][1] * inv,
                                          o[i][2] * inv, o[i][3] * inv);
        *(float4*)(dst + 4) = make_float4(o[i][4] * inv, o[i][5] * inv,
                                          o[i][6] * inv, o[i][7] * inv);
    }
}

// ---------------- host launcher ----------------
extern "C" void kernel_launch(void* const* d_in, const int* in_sizes, int n_in,
                              void* d_out, int out_size) {
    const int*   positions = (const int*)  d_in[0];
    const float* hidden    = (const float*)d_in[1];
    const float* w_qkv     = (const float*)d_in[2];
    const float* w_o       = (const float*)d_in[3];
    const float* q_norm_w  = (const float*)d_in[4];
    const float* k_norm_w  = (const float*)d_in[5];
    float*       out       = (float*)d_out;

    float *qkv_ptr, *attn_ptr;
    cudaGetSymbolAddress((void**)&qkv_ptr,  g_qkv);
    cudaGetSymbolAddress((void**)&attn_ptr, g_attn);

    cudaFuncSetAttribute(attention_kernel,
                         cudaFuncAttributeMaxDynamicSharedMemorySize, ATT_SMEM_BYTES);

    // 1) RoPE tables (independent)
    rope_table_kernel<<<(S_ * 64 + 255) / 256, 256>>>();

    // 2) QKV projection: [4096,4096] @ [4096,6144]
    gemm128_kernel<<<dim3(NQKV_ / 128, T_ / 128), 256>>>(
        hidden, w_qkv, qkv_ptr, T_, NQKV_, D_);

    // 3) RMSNorm + RoPE + layout
    normrope_kernel<<<T_, 256>>>(q_norm_w, k_norm_w, positions);

    // 4) causal GQA flash attention
    attention_kernel<<<dim3(S_ / 64, H_, B_), 256, ATT_SMEM_BYTES>>>();

    // 5) output projection: [4096,4096] @ [4096,4096] -> d_out
    gemm128_kernel<<<dim3(D_ / 128, T_ / 128), 256>>>(
        attn_ptr, w_o, out, T_, D_, H_ * HD_);
}

// round 12
// speedup vs baseline: 1.8663x; 1.8622x over previous
#include <cuda_runtime.h>
#include <math.h>
#include <stdint.h>

// ---------------- problem constants ----------------
#define B_   2
#define S_   2048
#define D_   4096
#define H_   32
#define KV_  8
#define HD_  128
#define T_   (B_ * S_)                 // 4096 tokens
#define NQKV_ ((H_ + 2 * KV_) * HD_)   // 6144
#define SCALE_ 0.08838834764831845f    // 1/sqrt(128)

// ---------------- device scratch (static globals: alloc-free rule) ----------------
__device__ __align__(16) float g_qkv[(size_t)T_ * NQKV_];            // [T, 6144]
__device__ __align__(16) float g_q  [(size_t)B_ * H_  * S_ * HD_];   // [B,H,S,HD]
__device__ __align__(16) float g_k  [(size_t)B_ * KV_ * S_ * HD_];   // [B,KV,S,HD]
__device__ __align__(16) float g_v  [(size_t)B_ * KV_ * S_ * HD_];   // [B,KV,S,HD]
__device__ __align__(16) float g_attn[(size_t)T_ * (H_ * HD_)];      // [T, 4096]
__device__ __align__(16) float g_cos[S_ * (HD_ / 2)];
__device__ __align__(16) float g_sin[S_ * (HD_ / 2)];

// ---------------- 1) RoPE cos/sin table (fp64 for angle precision) ----------------
__global__ void rope_table_kernel() {
    int idx = blockIdx.x * blockDim.x + threadIdx.x;
    if (idx >= S_ * 64) return;
    int p = idx >> 6;
    int i = idx & 63;
    double inv_freq = pow(10000.0, -(2.0 * (double)i) / 128.0);
    double ang = (double)p * inv_freq;
    g_cos[idx] = (float)cos(ang);
    g_sin[idx] = (float)sin(ang);
}

// ---------------- tf32 helpers ----------------
__device__ __forceinline__ float to_tf32(float x) {
    uint32_t u;
    asm("cvt.rna.tf32.f32 %0, %1;" : "=r"(u) : "f"(x));
    return __uint_as_float(u);
}

__device__ __forceinline__ void mma_tf32(float* d, const uint32_t* a, const uint32_t* b) {
    asm volatile(
        "mma.sync.aligned.m16n8k8.row.col.f32.tf32.tf32.f32 "
        "{%0,%1,%2,%3}, {%4,%5,%6,%7}, {%8,%9}, {%0,%1,%2,%3};\n"
        : "+f"(d[0]), "+f"(d[1]), "+f"(d[2]), "+f"(d[3])
        : "r"(a[0]), "r"(a[1]), "r"(a[2]), "r"(a[3]),
          "r"(b[0]), "r"(b[1]));
}

// ---------------- 2) tf32 tensor-core GEMM: C[M,N] = A[M,K] @ B[K,N] ----------------
// Block tile 128x128, k-tile 32. 8 warps: 4(m) x 2(n); warp tile 32x64.
// Smem padded to stride 136 -> conflict-free fragment LDS (banks = tig*8+gid).
#define GPAD 136

__global__ __launch_bounds__(256, 2) void gemm_tf32_kernel(
    const float* __restrict__ A, const float* __restrict__ Bm,
    float* __restrict__ C, int M, int N, int K)
{
    __shared__ float As[32][GPAD];   // [k][m]
    __shared__ float Bs[32][GPAD];   // [k][n]

    const int tid  = threadIdx.x;
    const int lane = tid & 31;
    const int warp = tid >> 5;
    const int gid  = lane >> 2;       // 0..7
    const int tig  = lane & 3;        // 0..3
    const int wm   = warp & 3;        // m-warp: rows wm*32
    const int wn   = warp >> 2;       // n-warp: cols wn*64

    const int m0 = blockIdx.y * 128;
    const int n0 = blockIdx.x * 128;

    // A-load assignment: thread t covers row arow, k-range [abase, abase+16)
    const int arow  = tid >> 1;            // 0..127
    const int abase = (tid & 1) * 16;      // 0 or 16
    // B-load assignment: thread t covers row brow, 4 float4's at bcol + i*32
    const int brow = tid >> 3;             // 0..31
    const int bcol = (tid & 7) * 4;        // 0..28

    float acc[2][8][4];
#pragma unroll
    for (int mt = 0; mt < 2; mt++)
#pragma unroll
        for (int nt = 0; nt < 8; nt++)
#pragma unroll
            for (int c = 0; c < 4; c++) acc[mt][nt][c] = 0.0f;

    for (int k0 = 0; k0 < K; k0 += 32) {
        // --- stage A tile (transposed into [k][m]) ---
        const float* Ag = A + (size_t)(m0 + arow) * K + k0 + abase;
#pragma unroll
        for (int i = 0; i < 4; i++) {
            float4 v = *(const float4*)(Ag + i * 4);
            int kc = abase + i * 4;
            As[kc + 0][arow] = to_tf32(v.x);
            As[kc + 1][arow] = to_tf32(v.y);
            As[kc + 2][arow] = to_tf32(v.z);
            As[kc + 3][arow] = to_tf32(v.w);
        }
        // --- stage B tile (natural [k][n]) ---
        const float* Bg = Bm + (size_t)(k0 + brow) * N + n0 + bcol;
#pragma unroll
        for (int i = 0; i < 4; i++) {
            float4 v = *(const float4*)(Bg + i * 32);
            float4 cv = make_float4(to_tf32(v.x), to_tf32(v.y),
                                    to_tf32(v.z), to_tf32(v.w));
            *(float4*)&Bs[brow][bcol + i * 32] = cv;
        }
        __syncthreads();

#pragma unroll
        for (int kk = 0; kk < 4; kk++) {
            const int kr = kk * 8 + tig;
            uint32_t a[2][4];
#pragma unroll
            for (int mt = 0; mt < 2; mt++) {
                int mr = wm * 32 + mt * 16 + gid;
                a[mt][0] = __float_as_uint(As[kr    ][mr    ]);
                a[mt][1] = __float_as_uint(As[kr    ][mr + 8]);
                a[mt][2] = __float_as_uint(As[kr + 4][mr    ]);
                a[mt][3] = __float_as_uint(As[kr + 4][mr + 8]);
            }
            uint32_t b[8][2];
#pragma unroll
            for (int nt = 0; nt < 8; nt++) {
                int nc = wn * 64 + nt * 8 + gid;
                b[nt][0] = __float_as_uint(Bs[kr    ][nc]);
                b[nt][1] = __float_as_uint(Bs[kr + 4][nc]);
            }
#pragma unroll
            for (int mt = 0; mt < 2; mt++)
#pragma unroll
                for (int nt = 0; nt < 8; nt++)
                    mma_tf32(acc[mt][nt], a[mt], b[nt]);
        }
        __syncthreads();
    }

    // --- epilogue ---
#pragma unroll
    for (int mt = 0; mt < 2; mt++) {
        int row = m0 + wm * 32 + mt * 16 + gid;
#pragma unroll
        for (int nt = 0; nt < 8; nt++) {
            int col = n0 + wn * 64 + nt * 8 + tig * 2;
            *(float2*)(C + (size_t)row * N + col) =
                make_float2(acc[mt][nt][0], acc[mt][nt][1]);
            *(float2*)(C + (size_t)(row + 8) * N + col) =
                make_float2(acc[mt][nt][2], acc[mt][nt][3]);
        }
    }
}

// ---------------- 3) fused per-head RMSNorm + RoPE + scatter ----------------
__global__ __launch_bounds__(256) void normrope_kernel(
    const float* __restrict__ q_norm_w, const float* __restrict__ k_norm_w,
    const int* __restrict__ positions)
{
    const int t    = blockIdx.x;            // token 0..4095
    const int lane = threadIdx.x & 31;
    const int warp = threadIdx.x >> 5;      // 0..7
    const int b = t >> 11;
    const int s = t & 2047;

    int p = positions[t];
    if (p < 0) p = 0;
    if (p >= S_) p = S_ - 1;

    const float* row = g_qkv + (size_t)t * NQKV_;

    for (int h = warp; h < (H_ + 2 * KV_); h += 8) {
        const float* x = row + h * HD_;
        float x0 = x[lane];
        float x1 = x[lane + 32];
        float x2 = x[lane + 64];
        float x3 = x[lane + 96];

        if (h < H_ + KV_) {
            float ss = x0 * x0 + x1 * x1 + x2 * x2 + x3 * x3;
#pragma unroll
            for (int off = 16; off >= 1; off >>= 1)
                ss += __shfl_xor_sync(0xffffffffu, ss, off);
            float r = rsqrtf(ss * (1.0f / 128.0f) + 1e-6f);

            const float* w = (h < H_) ? q_norm_w : k_norm_w;
            float y0 = x0 * r * w[lane];
            float y1 = x1 * r * w[lane + 32];
            float y2 = x2 * r * w[lane + 64];
            float y3 = x3 * r * w[lane + 96];

            float ca = g_cos[p * 64 + lane];
            float cb = g_cos[p * 64 + lane + 32];
            float sa = g_sin[p * 64 + lane];
            float sb = g_sin[p * 64 + lane + 32];

            float o0 = y0 * ca - y2 * sa;
            float o1 = y1 * cb - y3 * sb;
            float o2 = y2 * ca + y0 * sa;
            float o3 = y3 * cb + y1 * sb;

            float* dst;
            if (h < H_)
                dst = g_q + (((size_t)(b * H_ + h) * S_ + s) * HD_);
            else
                dst = g_k + (((size_t)(b * KV_ + (h - H_)) * S_ + s) * HD_);
            dst[lane]      = o0;
            dst[lane + 32] = o1;
            dst[lane + 64] = o2;
            dst[lane + 96] = o3;
        } else {
            float* dst = g_v + (((size_t)(b * KV_ + (h - H_ - KV_)) * S_ + s) * HD_);
            dst[lane]      = x0;
            dst[lane + 32] = x1;
            dst[lane + 64] = x2;
            dst[lane + 96] = x3;
        }
    }
}

// ---------------- 4) flash attention (causal GQA), fp32, online softmax ----------------
#define ATT_SMEM_FLOATS (128 * 64 + 128 * 64 + 64 * 128 + 64 * 64)  // 28672
#define ATT_SMEM_BYTES  (ATT_SMEM_FLOATS * 4)                       // 114688

__global__ __launch_bounds__(256) void attention_kernel() {
    extern __shared__ float sm[];
    float* Qs = sm;                       // [d][r]  d-major, 128x64
    float* Ks = Qs + 128 * 64;            // [d][c]  d-major, 128x64
    float* Vs = Ks + 128 * 64;            // [r][d]  natural, 64x128
    float* Ps = Vs + 64 * 128;            // [r][c]  64x64

    const int q0 = blockIdx.x;
    const int h  = blockIdx.y;
    const int b  = blockIdx.z;
    const int kh = h >> 2;

    const int tid = threadIdx.x;
    const int tx = tid & 15;
    const int ty = tid >> 4;

    const float* Q = g_q + ((size_t)(b * H_ + h) * S_ + q0 * 64) * HD_;
    const float* K = g_k + ((size_t)(b * KV_ + kh) * S_) * HD_;
    const float* V = g_v + ((size_t)(b * KV_ + kh) * S_) * HD_;

    for (int idx = tid; idx < 64 * 32; idx += 256) {
        int d4 = idx >> 6;
        int r  = idx & 63;
        float4 q = *(const float4*)(Q + (size_t)r * HD_ + d4 * 4);
        Qs[(d4 * 4 + 0) * 64 + r] = q.x;
        Qs[(d4 * 4 + 1) * 64 + r] = q.y;
        Qs[(d4 * 4 + 2) * 64 + r] = q.z;
        Qs[(d4 * 4 + 3) * 64 + r] = q.w;
    }

    float m[4], l[4], o[4][8];
#pragma unroll
    for (int i = 0; i < 4; i++) {
        m[i] = -1e30f;
        l[i] = 0.0f;
#pragma unroll
        for (int j = 0; j < 8; j++) o[i][j] = 0.0f;
    }

    for (int j0 = 0; j0 <= q0; j0++) {
        __syncthreads();

        const float* Kt = K + (size_t)j0 * 64 * HD_;
        for (int idx = tid; idx < 64 * 32; idx += 256) {
            int d4 = idx >> 6;
            int c  = idx & 63;
            float4 k = *(const float4*)(Kt + (size_t)c * HD_ + d4 * 4);
            Ks[(d4 * 4 + 0) * 64 + c] = k.x;
            Ks[(d4 * 4 + 1) * 64 + c] = k.y;
            Ks[(d4 * 4 + 2) * 64 + c] = k.z;
            Ks[(d4 * 4 + 3) * 64 + c] = k.w;
        }
        const float* Vt = V + (size_t)j0 * 64 * HD_;
        for (int idx = tid; idx < 64 * 32; idx += 256) {
            int r  = idx >> 5;
            int d4 = (idx & 31) * 4;
            *(float4*)(Vs + r * 128 + d4) = *(const float4*)(Vt + (size_t)r * HD_ + d4);
        }
        __syncthreads();

        float sacc[4][4];
#pragma unroll
        for (int i = 0; i < 4; i++)
#pragma unroll
            for (int j = 0; j < 4; j++) sacc[i][j] = 0.0f;

#pragma unroll 4
        for (int d = 0; d < 128; d++) {
            float4 qv = *(const float4*)(Qs + d * 64 + ty * 4);
            float4 kv = *(const float4*)(Ks + d * 64 + tx * 4);
            float qa[4] = {qv.x, qv.y, qv.z, qv.w};
            float ka[4] = {kv.x, kv.y, kv.z, kv.w};
#pragma unroll
            for (int i = 0; i < 4; i++)
#pragma unroll
                for (int j = 0; j < 4; j++)
                    sacc[i][j] += qa[i] * ka[j];
        }

#pragma unroll
        for (int i = 0; i < 4; i++)
#pragma unroll
            for (int j = 0; j < 4; j++) sacc[i][j] *= SCALE_;

        if (j0 == q0) {
#pragma unroll
            for (int i = 0; i < 4; i++)
#pragma unroll
                for (int j = 0; j < 4; j++)
                    if (tx * 4 + j > ty * 4 + i) sacc[i][j] = -1e30f;
        }

#pragma unroll
        for (int i = 0; i < 4; i++) {
            float rm = fmaxf(fmaxf(sacc[i][0], sacc[i][1]),
                             fmaxf(sacc[i][2], sacc[i][3]));
#pragma unroll
            for (int off = 8; off >= 1; off >>= 1)
                rm = fmaxf(rm, __shfl_xor_sync(0xffffffffu, rm, off));
            float mn   = fmaxf(m[i], rm);
            float corr = __expf(m[i] - mn);
            float p0 = __expf(sacc[i][0] - mn);
            float p1 = __expf(sacc[i][1] - mn);
            float p2 = __expf(sacc[i][2] - mn);
            float p3 = __expf(sacc[i][3] - mn);
            float rs = p0 + p1 + p2 + p3;
#pragma unroll
            for (int off = 8; off >= 1; off >>= 1)
                rs += __shfl_xor_sync(0xffffffffu, rs, off);
            l[i] = l[i] * corr + rs;
            m[i] = mn;
#pragma unroll
            for (int j = 0; j < 8; j++) o[i][j] *= corr;
            *(float4*)(Ps + (ty * 4 + i) * 64 + tx * 4) = make_float4(p0, p1, p2, p3);
        }
        __syncthreads();

#pragma unroll 2
        for (int jj = 0; jj < 64; jj++) {
            float pr[4];
#pragma unroll
            for (int i = 0; i < 4; i++) pr[i] = Ps[(ty * 4 + i) * 64 + jj];
            float4 v0 = *(const float4*)(Vs + jj * 128 + tx * 8);
            float4 v1 = *(const float4*)(Vs + jj * 128 + tx * 8 + 4);
            float va[8] = {v0.x, v0.y, v0.z, v0.w, v1.x, v1.y, v1.z, v1.w};
#pragma unroll
            for (int i = 0; i < 4; i++)
#pragma unroll
                for (int j = 0; j < 8; j++)
                    o[i][j] += pr[i] * va[j];
        }
    }

#pragma unroll
    for (int i = 0; i < 4; i++) {
        float inv = 1.0f / l[i];
        int r = q0 * 64 + ty * 4 + i;
        float* dst = g_attn + ((size_t)(b * S_ + r) * H_ + h) * HD_ + tx * 8;
        *(float4*)(dst + 0) = make_float4(o[i][0] * inv, o[i][1] * inv,
                                          o[i][2] * inv, o[i][3] * inv);
        *(float4*)(dst + 4) = make_float4(o[i][4] * inv, o[i][5] * inv,
                                          o[i][6] * inv, o[i][7] * inv);
    }
}

// ---------------- host launcher ----------------
extern "C" void kernel_launch(void* const* d_in, const int* in_sizes, int n_in,
                              void* d_out, int out_size) {
    const int*   positions = (const int*)  d_in[0];
    const float* hidden    = (const float*)d_in[1];
    const float* w_qkv     = (const float*)d_in[2];
    const float* w_o       = (const float*)d_in[3];
    const float* q_norm_w  = (const float*)d_in[4];
    const float* k_norm_w  = (const float*)d_in[5];
    float*       out       = (float*)d_out;

    float *qkv_ptr, *attn_ptr;
    cudaGetSymbolAddress((void**)&qkv_ptr,  g_qkv);
    cudaGetSymbolAddress((void**)&attn_ptr, g_attn);

    cudaFuncSetAttribute(attention_kernel,
                         cudaFuncAttributeMaxDynamicSharedMemorySize, ATT_SMEM_BYTES);

    // 1) RoPE tables
    rope_table_kernel<<<(S_ * 64 + 255) / 256, 256>>>();

    // 2) QKV projection: [4096,4096] @ [4096,6144]  (tf32 tensor cores)
    gemm_tf32_kernel<<<dim3(NQKV_ / 128, T_ / 128), 256>>>(
        hidden, w_qkv, qkv_ptr, T_, NQKV_, D_);

    // 3) RMSNorm + RoPE + layout
    normrope_kernel<<<T_, 256>>>(q_norm_w, k_norm_w, positions);

    // 4) causal GQA flash attention
    attention_kernel<<<dim3(S_ / 64, H_, B_), 256, ATT_SMEM_BYTES>>>();

    // 5) output projection: [4096,4096] @ [4096,4096] -> d_out  (tf32 tensor cores)
    gemm_tf32_kernel<<<dim3(D_ / 128, T_ / 128), 256>>>(
        attn_ptr, w_o, out, T_, D_, H_ * HD_);
}

// round 13
// speedup vs baseline: 1.8673x; 1.0005x over previous
#include <cuda_runtime.h>
#include <math.h>
#include <stdint.h>

// ---------------- problem constants ----------------
#define B_   2
#define S_   2048
#define D_   4096
#define H_   32
#define KV_  8
#define HD_  128
#define T_   (B_ * S_)                 // 4096 tokens
#define NQKV_ ((H_ + 2 * KV_) * HD_)   // 6144
#define SCALE_ 0.08838834764831845f    // 1/sqrt(128)

// ---------------- device scratch (static globals: alloc-free rule) ----------------
__device__ __align__(16) float g_qkv[(size_t)T_ * NQKV_];            // [T, 6144]
__device__ __align__(16) float g_q  [(size_t)B_ * H_  * S_ * HD_];   // [B,H,S,HD]
__device__ __align__(16) float g_k  [(size_t)B_ * KV_ * S_ * HD_];   // [B,KV,S,HD]
__device__ __align__(16) float g_v  [(size_t)B_ * KV_ * S_ * HD_];   // [B,KV,S,HD]
__device__ __align__(16) float g_attn[(size_t)T_ * (H_ * HD_)];      // [T, 4096]
__device__ __align__(16) float g_cos[S_ * (HD_ / 2)];
__device__ __align__(16) float g_sin[S_ * (HD_ / 2)];

// ---------------- 1) RoPE cos/sin table (fp64 for angle precision) ----------------
__global__ void rope_table_kernel() {
    int idx = blockIdx.x * blockDim.x + threadIdx.x;
    if (idx >= S_ * 64) return;
    int p = idx >> 6;
    int i = idx & 63;
    double inv_freq = pow(10000.0, -(2.0 * (double)i) / 128.0);
    double ang = (double)p * inv_freq;
    g_cos[idx] = (float)cos(ang);
    g_sin[idx] = (float)sin(ang);
}

// ---------------- tf32 helpers ----------------
__device__ __forceinline__ float to_tf32(float x) {
    uint32_t u;
    asm("cvt.rna.tf32.f32 %0, %1;" : "=r"(u) : "f"(x));
    return __uint_as_float(u);
}

__device__ __forceinline__ void mma_tf32(float* d, const uint32_t* a, const uint32_t* b) {
    asm volatile(
        "mma.sync.aligned.m16n8k8.row.col.f32.tf32.tf32.f32 "
        "{%0,%1,%2,%3}, {%4,%5,%6,%7}, {%8,%9}, {%0,%1,%2,%3};\n"
        : "+f"(d[0]), "+f"(d[1]), "+f"(d[2]), "+f"(d[3])
        : "r"(a[0]), "r"(a[1]), "r"(a[2]), "r"(a[3]),
          "r"(b[0]), "r"(b[1]));
}

// ---------------- 2) tf32 tensor-core GEMM: C[M,N] = A[M,K] @ B[K,N] ----------------
// Block tile 128x128, k-tile 32. 8 warps: 4(m) x 2(n); warp tile 32x64.
// Smem padded to stride 136 -> conflict-free fragment LDS (banks = tig*8+gid).
#define GPAD 136

__global__ __launch_bounds__(256, 2) void gemm_tf32_kernel(
    const float* __restrict__ A, const float* __restrict__ Bm,
    float* __restrict__ C, int M, int N, int K)
{
    __shared__ float As[32][GPAD];   // [k][m]
    __shared__ float Bs[32][GPAD];   // [k][n]

    const int tid  = threadIdx.x;
    const int lane = tid & 31;
    const int warp = tid >> 5;
    const int gid  = lane >> 2;       // 0..7
    const int tig  = lane & 3;        // 0..3
    const int wm   = warp & 3;        // m-warp: rows wm*32
    const int wn   = warp >> 2;       // n-warp: cols wn*64

    const int m0 = blockIdx.y * 128;
    const int n0 = blockIdx.x * 128;

    // A-load assignment: thread t covers row arow, k-range [abase, abase+16)
    const int arow  = tid >> 1;            // 0..127
    const int abase = (tid & 1) * 16;      // 0 or 16
    // B-load assignment: thread t covers row brow, 4 float4's at bcol + i*32
    const int brow = tid >> 3;             // 0..31
    const int bcol = (tid & 7) * 4;        // 0..28

    float acc[2][8][4];
#pragma unroll
    for (int mt = 0; mt < 2; mt++)
#pragma unroll
        for (int nt = 0; nt < 8; nt++)
#pragma unroll
            for (int c = 0; c < 4; c++) acc[mt][nt][c] = 0.0f;

    for (int k0 = 0; k0 < K; k0 += 32) {
        // --- stage A tile (transposed into [k][m]) ---
        const float* Ag = A + (size_t)(m0 + arow) * K + k0 + abase;
#pragma unroll
        for (int i = 0; i < 4; i++) {
            float4 v = *(const float4*)(Ag + i * 4);
            int kc = abase + i * 4;
            As[kc + 0][arow] = to_tf32(v.x);
            As[kc + 1][arow] = to_tf32(v.y);
            As[kc + 2][arow] = to_tf32(v.z);
            As[kc + 3][arow] = to_tf32(v.w);
        }
        // --- stage B tile (natural [k][n]) ---
        const float* Bg = Bm + (size_t)(k0 + brow) * N + n0 + bcol;
#pragma unroll
        for (int i = 0; i < 4; i++) {
            float4 v = *(const float4*)(Bg + i * 32);
            float4 cv = make_float4(to_tf32(v.x), to_tf32(v.y),
                                    to_tf32(v.z), to_tf32(v.w));
            *(float4*)&Bs[brow][bcol + i * 32] = cv;
        }
        __syncthreads();

#pragma unroll
        for (int kk = 0; kk < 4; kk++) {
            const int kr = kk * 8 + tig;
            uint32_t a[2][4];
#pragma unroll
            for (int mt = 0; mt < 2; mt++) {
                int mr = wm * 32 + mt * 16 + gid;
                a[mt][0] = __float_as_uint(As[kr    ][mr    ]);
                a[mt][1] = __float_as_uint(As[kr    ][mr + 8]);
                a[mt][2] = __float_as_uint(As[kr + 4][mr    ]);
                a[mt][3] = __float_as_uint(As[kr + 4][mr + 8]);
            }
            uint32_t b[8][2];
#pragma unroll
            for (int nt = 0; nt < 8; nt++) {
                int nc = wn * 64 + nt * 8 + gid;
                b[nt][0] = __float_as_uint(Bs[kr    ][nc]);
                b[nt][1] = __float_as_uint(Bs[kr + 4][nc]);
            }
#pragma unroll
            for (int mt = 0; mt < 2; mt++)
#pragma unroll
                for (int nt = 0; nt < 8; nt++)
                    mma_tf32(acc[mt][nt], a[mt], b[nt]);
        }
        __syncthreads();
    }

    // --- epilogue ---
#pragma unroll
    for (int mt = 0; mt < 2; mt++) {
        int row = m0 + wm * 32 + mt * 16 + gid;
#pragma unroll
        for (int nt = 0; nt < 8; nt++) {
            int col = n0 + wn * 64 + nt * 8 + tig * 2;
            *(float2*)(C + (size_t)row * N + col) =
                make_float2(acc[mt][nt][0], acc[mt][nt][1]);
            *(float2*)(C + (size_t)(row + 8) * N + col) =
                make_float2(acc[mt][nt][2], acc[mt][nt][3]);
        }
    }
}

// ---------------- 3) fused per-head RMSNorm + RoPE + scatter ----------------
__global__ __launch_bounds__(256) void normrope_kernel(
    const float* __restrict__ q_norm_w, const float* __restrict__ k_norm_w,
    const int* __restrict__ positions)
{
    const int t    = blockIdx.x;            // token 0..4095
    const int lane = threadIdx.x & 31;
    const int warp = threadIdx.x >> 5;      // 0..7
    const int b = t >> 11;
    const int s = t & 2047;

    int p = positions[t];
    if (p < 0) p = 0;
    if (p >= S_) p = S_ - 1;

    const float* row = g_qkv + (size_t)t * NQKV_;

    for (int h = warp; h < (H_ + 2 * KV_); h += 8) {
        const float* x = row + h * HD_;
        float x0 = x[lane];
        float x1 = x[lane + 32];
        float x2 = x[lane + 64];
        float x3 = x[lane + 96];

        if (h < H_ + KV_) {
            float ss = x0 * x0 + x1 * x1 + x2 * x2 + x3 * x3;
#pragma unroll
            for (int off = 16; off >= 1; off >>= 1)
                ss += __shfl_xor_sync(0xffffffffu, ss, off);
            float r = rsqrtf(ss * (1.0f / 128.0f) + 1e-6f);

            const float* w = (h < H_) ? q_norm_w : k_norm_w;
            float y0 = x0 * r * w[lane];
            float y1 = x1 * r * w[lane + 32];
            float y2 = x2 * r * w[lane + 64];
            float y3 = x3 * r * w[lane + 96];

            float ca = g_cos[p * 64 + lane];
            float cb = g_cos[p * 64 + lane + 32];
            float sa = g_sin[p * 64 + lane];
            float sb = g_sin[p * 64 + lane + 32];

            float o0 = y0 * ca - y2 * sa;
            float o1 = y1 * cb - y3 * sb;
            float o2 = y2 * ca + y0 * sa;
            float o3 = y3 * cb + y1 * sb;

            float* dst;
            if (h < H_)
                dst = g_q + (((size_t)(b * H_ + h) * S_ + s) * HD_);
            else
                dst = g_k + (((size_t)(b * KV_ + (h - H_)) * S_ + s) * HD_);
            dst[lane]      = o0;
            dst[lane + 32] = o1;
            dst[lane + 64] = o2;
            dst[lane + 96] = o3;
        } else {
            float* dst = g_v + (((size_t)(b * KV_ + (h - H_ - KV_)) * S_ + s) * HD_);
            dst[lane]      = x0;
            dst[lane + 32] = x1;
            dst[lane + 64] = x2;
            dst[lane + 96] = x3;
        }
    }
}

// ---------------- 4) flash attention (causal GQA), fp32, online softmax ----------------
#define ATT_SMEM_FLOATS (128 * 64 + 128 * 64 + 64 * 128 + 64 * 64)  // 28672
#define ATT_SMEM_BYTES  (ATT_SMEM_FLOATS * 4)                       // 114688

__global__ __launch_bounds__(256) void attention_kernel() {
    extern __shared__ float sm[];
    float* Qs = sm;                       // [d][r]  d-major, 128x64
    float* Ks = Qs + 128 * 64;            // [d][c]  d-major, 128x64
    float* Vs = Ks + 128 * 64;            // [r][d]  natural, 64x128
    float* Ps = Vs + 64 * 128;            // [r][c]  64x64

    const int q0 = blockIdx.x;
    const int h  = blockIdx.y;
    const int b  = blockIdx.z;
    const int kh = h >> 2;

    const int tid = threadIdx.x;
    const int tx = tid & 15;
    const int ty = tid >> 4;

    const float* Q = g_q + ((size_t)(b * H_ + h) * S_ + q0 * 64) * HD_;
    const float* K = g_k + ((size_t)(b * KV_ + kh) * S_) * HD_;
    const float* V = g_v + ((size_t)(b * KV_ + kh) * S_) * HD_;

    for (int idx = tid; idx < 64 * 32; idx += 256) {
        int d4 = idx >> 6;
        int r  = idx & 63;
        float4 q = *(const float4*)(Q + (size_t)r * HD_ + d4 * 4);
        Qs[(d4 * 4 + 0) * 64 + r] = q.x;
        Qs[(d4 * 4 + 1) * 64 + r] = q.y;
        Qs[(d4 * 4 + 2) * 64 + r] = q.z;
        Qs[(d4 * 4 + 3) * 64 + r] = q.w;
    }

    float m[4], l[4], o[4][8];
#pragma unroll
    for (int i = 0; i < 4; i++) {
        m[i] = -1e30f;
        l[i] = 0.0f;
#pragma unroll
        for (int j = 0; j < 8; j++) o[i][j] = 0.0f;
    }

    for (int j0 = 0; j0 <= q0; j0++) {
        __syncthreads();

        const float* Kt = K + (size_t)j0 * 64 * HD_;
        for (int idx = tid; idx < 64 * 32; idx += 256) {
            int d4 = idx >> 6;
            int c  = idx & 63;
            float4 k = *(const float4*)(Kt + (size_t)c * HD_ + d4 * 4);
            Ks[(d4 * 4 + 0) * 64 + c] = k.x;
            Ks[(d4 * 4 + 1) * 64 + c] = k.y;
            Ks[(d4 * 4 + 2) * 64 + c] = k.z;
            Ks[(d4 * 4 + 3) * 64 + c] = k.w;
        }
        const float* Vt = V + (size_t)j0 * 64 * HD_;
        for (int idx = tid; idx < 64 * 32; idx += 256) {
            int r  = idx >> 5;
            int d4 = (idx & 31) * 4;
            *(float4*)(Vs + r * 128 + d4) = *(const float4*)(Vt + (size_t)r * HD_ + d4);
        }
        __syncthreads();

        float sacc[4][4];
#pragma unroll
        for (int i = 0; i < 4; i++)
#pragma unroll
            for (int j = 0; j < 4; j++) sacc[i][j] = 0.0f;

#pragma unroll 4
        for (int d = 0; d < 128; d++) {
            float4 qv = *(const float4*)(Qs + d * 64 + ty * 4);
            float4 kv = *(const float4*)(Ks + d * 64 + tx * 4);
            float qa[4] = {qv.x, qv.y, qv.z, qv.w};
            float ka[4] = {kv.x, kv.y, kv.z, kv.w};
#pragma unroll
            for (int i = 0; i < 4; i++)
#pragma unroll
                for (int j = 0; j < 4; j++)
                    sacc[i][j] += qa[i] * ka[j];
        }

#pragma unroll
        for (int i = 0; i < 4; i++)
#pragma unroll
            for (int j = 0; j < 4; j++) sacc[i][j] *= SCALE_;

        if (j0 == q0) {
#pragma unroll
            for (int i = 0; i < 4; i++)
#pragma unroll
                for (int j = 0; j < 4; j++)
                    if (tx * 4 + j > ty * 4 + i) sacc[i][j] = -1e30f;
        }

#pragma unroll
        for (int i = 0; i < 4; i++) {
            float rm = fmaxf(fmaxf(sacc[i][0], sacc[i][1]),
                             fmaxf(sacc[i][2], sacc[i][3]));
#pragma unroll
            for (int off = 8; off >= 1; off >>= 1)
                rm = fmaxf(rm, __shfl_xor_sync(0xffffffffu, rm, off));
            float mn   = fmaxf(m[i], rm);
            float corr = __expf(m[i] - mn);
            float p0 = __expf(sacc[i][0] - mn);
            float p1 = __expf(sacc[i][1] - mn);
            float p2 = __expf(sacc[i][2] - mn);
            float p3 = __expf(sacc[i][3] - mn);
            float rs = p0 + p1 + p2 + p3;
#pragma unroll
            for (int off = 8; off >= 1; off >>= 1)
                rs += __shfl_xor_sync(0xffffffffu, rs, off);
            l[i] = l[i] * corr + rs;
            m[i] = mn;
#pragma unroll
            for (int j = 0; j < 8; j++) o[i][j] *= corr;
            *(float4*)(Ps + (ty * 4 + i) * 64 + tx * 4) = make_float4(p0, p1, p2, p3);
        }
        __syncthreads();

#pragma unroll 2
        for (int jj = 0; jj < 64; jj++) {
            float pr[4];
#pragma unroll
            for (int i = 0; i < 4; i++) pr[i] = Ps[(ty * 4 + i) * 64 + jj];
            float4 v0 = *(const float4*)(Vs + jj * 128 + tx * 8);
            float4 v1 = *(const float4*)(Vs + jj * 128 + tx * 8 + 4);
            float va[8] = {v0.x, v0.y, v0.z, v0.w, v1.x, v1.y, v1.z, v1.w};
#pragma unroll
            for (int i = 0; i < 4; i++)
#pragma unroll
                for (int j = 0; j < 8; j++)
                    o[i][j] += pr[i] * va[j];
        }
    }

#pragma unroll
    for (int i = 0; i < 4; i++) {
        float inv = 1.0f / l[i];
        int r = q0 * 64 + ty * 4 + i;
        float* dst = g_attn + ((size_t)(b * S_ + r) * H_ + h) * HD_ + tx * 8;
        *(float4*)(dst + 0) = make_float4(o[i][0] * inv, o[i][1] * inv,
                                          o[i][2] * inv, o[i][3] * inv);
        *(float4*)(dst + 4) = make_float4(o[i][4] * inv, o[i][5] * inv,
                                          o[i][6] * inv, o[i][7] * inv);
    }
}

// ---------------- host launcher ----------------
extern "C" void kernel_launch(void* const* d_in, const int* in_sizes, int n_in,
                              void* d_out, int out_size) {
    const int*   positions = (const int*)  d_in[0];
    const float* hidden    = (const float*)d_in[1];
    const float* w_qkv     = (const float*)d_in[2];
    const float* w_o       = (const float*)d_in[3];
    const float* q_norm_w  = (const float*)d_in[4];
    const float* k_norm_w  = (const float*)d_in[5];
    float*       out       = (float*)d_out;

    float *qkv_ptr, *attn_ptr;
    cudaGetSymbolAddress((void**)&qkv_ptr,  g_qkv);
    cudaGetSymbolAddress((void**)&attn_ptr, g_attn);

    cudaFuncSetAttribute(attention_kernel,
                         cudaFuncAttributeMaxDynamicSharedMemorySize, ATT_SMEM_BYTES);

    // 1) RoPE tables
    rope_table_kernel<<<(S_ * 64 + 255) / 256, 256>>>();

    // 2) QKV projection: [4096,4096] @ [4096,6144]  (tf32 tensor cores)
    gemm_tf32_kernel<<<dim3(NQKV_ / 128, T_ / 128), 256>>>(
        hidden, w_qkv, qkv_ptr, T_, NQKV_, D_);

    // 3) RMSNorm + RoPE + layout
    normrope_kernel<<<T_, 256>>>(q_norm_w, k_norm_w, positions);

    // 4) causal GQA flash attention
    attention_kernel<<<dim3(S_ / 64, H_, B_), 256, ATT_SMEM_BYTES>>>();

    // 5) output projection: [4096,4096] @ [4096,4096] -> d_out  (tf32 tensor cores)
    gemm_tf32_kernel<<<dim3(D_ / 128, T_ / 128), 256>>>(
        attn_ptr, w_o, out, T_, D_, H_ * HD_);
}

// round 15
// speedup vs baseline: 2.0449x; 1.0951x over previous
#include <cuda_runtime.h>
#include <math.h>
#include <stdint.h>

// ---------------- problem constants ----------------
#define B_   2
#define S_   2048
#define D_   4096
#define H_   32
#define KV_  8
#define HD_  128
#define T_   (B_ * S_)                 // 4096 tokens
#define NQKV_ ((H_ + 2 * KV_) * HD_)   // 6144
#define SCALE_ 0.08838834764831845f    // 1/sqrt(128)

// ---------------- device scratch (static globals: alloc-free rule) ----------------
__device__ __align__(16) float g_qkv[(size_t)T_ * NQKV_];            // [T, 6144]
__device__ __align__(16) float g_q  [(size_t)B_ * H_  * S_ * HD_];   // [B,H,S,HD]
__device__ __align__(16) float g_k  [(size_t)B_ * KV_ * S_ * HD_];   // [B,KV,S,HD]
__device__ __align__(16) float g_v  [(size_t)B_ * KV_ * S_ * HD_];   // [B,KV,S,HD]
__device__ __align__(16) float g_attn[(size_t)T_ * (H_ * HD_)];      // [T, 4096]
__device__ __align__(16) float g_cos[S_ * (HD_ / 2)];
__device__ __align__(16) float g_sin[S_ * (HD_ / 2)];
// tf32-prerounded copies of GEMM operands
__device__ __align__(16) float g_hidden[(size_t)T_ * D_];
__device__ __align__(16) float g_wqkv[(size_t)D_ * NQKV_];
__device__ __align__(16) float g_wo[(size_t)(H_ * HD_) * D_];

// ---------------- tf32 helpers ----------------
__device__ __forceinline__ float to_tf32(float x) {
    uint32_t u;
    asm("cvt.rna.tf32.f32 %0, %1;" : "=r"(u) : "f"(x));
    return __uint_as_float(u);
}

__device__ __forceinline__ void mma_tf32(float* d, const uint32_t* a, const uint32_t* b) {
    asm volatile(
        "mma.sync.aligned.m16n8k8.row.col.f32.tf32.tf32.f32 "
        "{%0,%1,%2,%3}, {%4,%5,%6,%7}, {%8,%9}, {%0,%1,%2,%3};\n"
        : "+f"(d[0]), "+f"(d[1]), "+f"(d[2]), "+f"(d[3])
        : "r"(a[0]), "r"(a[1]), "r"(a[2]), "r"(a[3]),
          "r"(b[0]), "r"(b[1]));
}

__device__ __forceinline__ void cp_async16(uint32_t dst, const void* src) {
    asm volatile("cp.async.cg.shared.global [%0], [%1], 16;\n"
                 :: "r"(dst), "l"(src));
}
__device__ __forceinline__ void cp_commit() {
    asm volatile("cp.async.commit_group;\n");
}
template <int N>
__device__ __forceinline__ void cp_wait() {
    asm volatile("cp.async.wait_group %0;\n" :: "n"(N));
}

// ---------------- 0) tf32 pre-rounding pass ----------------
__global__ __launch_bounds__(256) void cvt_tf32_kernel(
    const float* __restrict__ src, float* __restrict__ dst, int n)
{
    int i = (blockIdx.x * blockDim.x + threadIdx.x) * 4;
    if (i >= n) return;
    float4 v = *(const float4*)(src + i);
    v.x = to_tf32(v.x); v.y = to_tf32(v.y);
    v.z = to_tf32(v.z); v.w = to_tf32(v.w);
    *(float4*)(dst + i) = v;
}

// ---------------- 1) RoPE cos/sin table (fp64 for angle precision) ----------------
__global__ void rope_table_kernel() {
    int idx = blockIdx.x * blockDim.x + threadIdx.x;
    if (idx >= S_ * 64) return;
    int p = idx >> 6;
    int i = idx & 63;
    double inv_freq = pow(10000.0, -(2.0 * (double)i) / 128.0);
    double ang = (double)p * inv_freq;
    g_cos[idx] = (float)cos(ang);
    g_sin[idx] = (float)sin(ang);
}

// ---------------- 2) tf32 GEMM, cp.async double-buffered ----------------
// C[M,N] = A[M,K] @ B[K,N], inputs pre-rounded to tf32.
// Block tile 128x128, k-tile 32, 2 smem stages. 8 warps: 4(m) x 2(n), warp 32x64.
// A smem [m][k] stride 36  -> fragment banks 4*gid+tig (conflict-free)
// B smem [k][n] stride 136 -> fragment banks 8*tig+gid (conflict-free)
#define GA 36
#define GB 136
#define A_STG (128 * GA)                       // 4608 floats / stage
#define B_STG (32 * GB)                        // 4352 floats / stage
#define GEMM_SMEM_BYTES ((2 * (A_STG + B_STG)) * 4)  // 71680 B

__global__ __launch_bounds__(256, 2) void gemm_tf32_db_kernel(
    const float* __restrict__ A, const float* __restrict__ Bm,
    float* __restrict__ C, int M, int N, int K)
{
    extern __shared__ float sm[];
    float* As = sm;                    // [2][128][GA]
    float* Bs = sm + 2 * A_STG;        // [2][32][GB]
    const uint32_t as_u = (uint32_t)__cvta_generic_to_shared(As);
    const uint32_t bs_u = (uint32_t)__cvta_generic_to_shared(Bs);

    const int tid  = threadIdx.x;
    const int lane = tid & 31;
    const int warp = tid >> 5;
    const int gid  = lane >> 2;        // 0..7
    const int tig  = lane & 3;         // 0..3
    const int wm   = warp & 3;         // m-warp
    const int wn   = warp >> 2;        // n-warp

    const int m0 = blockIdx.y * 128;
    const int n0 = blockIdx.x * 128;

    // A staging: thread covers row arow, 16-float half (tid&1), 4 quads
    const int arow  = tid >> 1;            // 0..127
    const int acol  = (tid & 1) * 16;      // 0 or 16
    // B staging: thread covers k-row brow, quads at columns bcol + i*32
    const int brow = tid >> 3;             // 0..31
    const int bcol = (tid & 7) * 4;        // 0..28

    const float* Ag0 = A  + (size_t)(m0 + arow) * K + acol;
    const float* Bg0 = Bm + (size_t)brow * N + n0 + bcol;

    float acc[2][8][4];
#pragma unroll
    for (int mt = 0; mt < 2; mt++)
#pragma unroll
        for (int nt = 0; nt < 8; nt++)
#pragma unroll
            for (int c = 0; c < 4; c++) acc[mt][nt][c] = 0.0f;

    // ---- prologue: stage k0=0 into buffer 0 ----
    {
        uint32_t ad = as_u + (uint32_t)((arow * GA + acol) * 4);
        const float* ag = Ag0;
#pragma unroll
        for (int i = 0; i < 4; i++)
            cp_async16(ad + i * 16, ag + i * 4);          // dst step 16 B = 4 floats
        uint32_t bd = bs_u + (uint32_t)((brow * GB + bcol) * 4);
        const float* bg = Bg0;
#pragma unroll
        for (int i = 0; i < 4; i++)
            cp_async16(bd + i * 128, bg + i * 32);        // dst step 128 B = 32 floats
        cp_commit();
    }

    int buf = 0;
#pragma unroll 1
    for (int k0 = 0; k0 < K; k0 += 32) {
        if (k0 + 32 < K) {
            // stage next tile into buf^1
            int nb = buf ^ 1;
            uint32_t ad = as_u + (uint32_t)((nb * A_STG + arow * GA + acol) * 4);
            const float* ag = Ag0 + k0 + 32;
#pragma unroll
            for (int i = 0; i < 4; i++)
                cp_async16(ad + i * 16, ag + i * 4);
            uint32_t bd = bs_u + (uint32_t)((nb * B_STG + brow * GB + bcol) * 4);
            const float* bg = Bg0 + (size_t)(k0 + 32) * N;
#pragma unroll
            for (int i = 0; i < 4; i++)
                cp_async16(bd + i * 128, bg + i * 32);    // FIXED: 128 B, not 512 B
            cp_commit();
            cp_wait<1>();
        } else {
            cp_wait<0>();
        }
        __syncthreads();

        const float* ca = As + buf * A_STG;
        const float* cb = Bs + buf * B_STG;

#pragma unroll
        for (int kk = 0; kk < 4; kk++) {
            const int kr = kk * 8 + tig;
            uint32_t a[2][4];
#pragma unroll
            for (int mt = 0; mt < 2; mt++) {
                int mr = wm * 32 + mt * 16 + gid;
                a[mt][0] = __float_as_uint(ca[(mr    ) * GA + kr    ]);
                a[mt][1] = __float_as_uint(ca[(mr + 8) * GA + kr    ]);
                a[mt][2] = __float_as_uint(ca[(mr    ) * GA + kr + 4]);
                a[mt][3] = __float_as_uint(ca[(mr + 8) * GA + kr + 4]);
            }
            uint32_t b[8][2];
#pragma unroll
            for (int nt = 0; nt < 8; nt++) {
                int nc = wn * 64 + nt * 8 + gid;
                b[nt][0] = __float_as_uint(cb[(kr    ) * GB + nc]);
                b[nt][1] = __float_as_uint(cb[(kr + 4) * GB + nc]);
            }
#pragma unroll
            for (int mt = 0; mt < 2; mt++)
#pragma unroll
                for (int nt = 0; nt < 8; nt++)
                    mma_tf32(acc[mt][nt], a[mt], b[nt]);
        }
        __syncthreads();   // protect buf from next iteration's cp.async overwrite
        buf ^= 1;
    }

    // ---- epilogue ----
#pragma unroll
    for (int mt = 0; mt < 2; mt++) {
        int row = m0 + wm * 32 + mt * 16 + gid;
#pragma unroll
        for (int nt = 0; nt < 8; nt++) {
            int col = n0 + wn * 64 + nt * 8 + tig * 2;
            *(float2*)(C + (size_t)row * N + col) =
                make_float2(acc[mt][nt][0], acc[mt][nt][1]);
            *(float2*)(C + (size_t)(row + 8) * N + col) =
                make_float2(acc[mt][nt][2], acc[mt][nt][3]);
        }
    }
}

// ---------------- 3) fused per-head RMSNorm + RoPE + scatter ----------------
__global__ __launch_bounds__(256) void normrope_kernel(
    const float* __restrict__ q_norm_w, const float* __restrict__ k_norm_w,
    const int* __restrict__ positions)
{
    const int t    = blockIdx.x;            // token 0..4095
    const int lane = threadIdx.x & 31;
    const int warp = threadIdx.x >> 5;      // 0..7
    const int b = t >> 11;
    const int s = t & 2047;

    int p = positions[t];
    if (p < 0) p = 0;
    if (p >= S_) p = S_ - 1;

    const float* row = g_qkv + (size_t)t * NQKV_;

    for (int h = warp; h < (H_ + 2 * KV_); h += 8) {
        const float* x = row + h * HD_;
        float x0 = x[lane];
        float x1 = x[lane + 32];
        float x2 = x[lane + 64];
        float x3 = x[lane + 96];

        if (h < H_ + KV_) {
            float ss = x0 * x0 + x1 * x1 + x2 * x2 + x3 * x3;
#pragma unroll
            for (int off = 16; off >= 1; off >>= 1)
                ss += __shfl_xor_sync(0xffffffffu, ss, off);
            float r = rsqrtf(ss * (1.0f / 128.0f) + 1e-6f);

            const float* w = (h < H_) ? q_norm_w : k_norm_w;
            float y0 = x0 * r * w[lane];
            float y1 = x1 * r * w[lane + 32];
            float y2 = x2 * r * w[lane + 64];
            float y3 = x3 * r * w[lane + 96];

            float ca = g_cos[p * 64 + lane];
            float cb = g_cos[p * 64 + lane + 32];
            float sa = g_sin[p * 64 + lane];
            float sb = g_sin[p * 64 + lane + 32];

            float o0 = y0 * ca - y2 * sa;
            float o1 = y1 * cb - y3 * sb;
            float o2 = y2 * ca + y0 * sa;
            float o3 = y3 * cb + y1 * sb;

            float* dst;
            if (h < H_)
                dst = g_q + (((size_t)(b * H_ + h) * S_ + s) * HD_);
            else
                dst = g_k + (((size_t)(b * KV_ + (h - H_)) * S_ + s) * HD_);
            dst[lane]      = o0;
            dst[lane + 32] = o1;
            dst[lane + 64] = o2;
            dst[lane + 96] = o3;
        } else {
            float* dst = g_v + (((size_t)(b * KV_ + (h - H_ - KV_)) * S_ + s) * HD_);
            dst[lane]      = x0;
            dst[lane + 32] = x1;
            dst[lane + 64] = x2;
            dst[lane + 96] = x3;
        }
    }
}

// ---------------- 4) flash attention (causal GQA), fp32, online softmax ----------------
#define ATT_SMEM_FLOATS (128 * 64 + 128 * 64 + 64 * 128 + 64 * 64)  // 28672
#define ATT_SMEM_BYTES  (ATT_SMEM_FLOATS * 4)                       // 114688

__global__ __launch_bounds__(256) void attention_kernel() {
    extern __shared__ float sm[];
    float* Qs = sm;                       // [d][r]  d-major, 128x64
    float* Ks = Qs + 128 * 64;            // [d][c]  d-major, 128x64
    float* Vs = Ks + 128 * 64;            // [r][d]  natural, 64x128
    float* Ps = Vs + 64 * 128;            // [r][c]  64x64

    const int q0 = blockIdx.x;
    const int h  = blockIdx.y;
    const int b  = blockIdx.z;
    const int kh = h >> 2;

    const int tid = threadIdx.x;
    const int tx = tid & 15;
    const int ty = tid >> 4;

    const float* Q = g_q + ((size_t)(b * H_ + h) * S_ + q0 * 64) * HD_;
    const float* K = g_k + ((size_t)(b * KV_ + kh) * S_) * HD_;
    const float* V = g_v + ((size_t)(b * KV_ + kh) * S_) * HD_;

    for (int idx = tid; idx < 64 * 32; idx += 256) {
        int d4 = idx >> 6;
        int r  = idx & 63;
        float4 q = *(const float4*)(Q + (size_t)r * HD_ + d4 * 4);
        Qs[(d4 * 4 + 0) * 64 + r] = q.x;
        Qs[(d4 * 4 + 1) * 64 + r] = q.y;
        Qs[(d4 * 4 + 2) * 64 + r] = q.z;
        Qs[(d4 * 4 + 3) * 64 + r] = q.w;
    }

    float m[4], l[4], o[4][8];
#pragma unroll
    for (int i = 0; i < 4; i++) {
        m[i] = -1e30f;
        l[i] = 0.0f;
#pragma unroll
        for (int j = 0; j < 8; j++) o[i][j] = 0.0f;
    }

    for (int j0 = 0; j0 <= q0; j0++) {
        __syncthreads();

        const float* Kt = K + (size_t)j0 * 64 * HD_;
        for (int idx = tid; idx < 64 * 32; idx += 256) {
            int d4 = idx >> 6;
            int c  = idx & 63;
            float4 k = *(const float4*)(Kt + (size_t)c * HD_ + d4 * 4);
            Ks[(d4 * 4 + 0) * 64 + c] = k.x;
            Ks[(d4 * 4 + 1) * 64 + c] = k.y;
            Ks[(d4 * 4 + 2) * 64 + c] = k.z;
            Ks[(d4 * 4 + 3) * 64 + c] = k.w;
        }
        const float* Vt = V + (size_t)j0 * 64 * HD_;
        for (int idx = tid; idx < 64 * 32; idx += 256) {
            int r  = idx >> 5;
            int d4 = (idx & 31) * 4;
            *(float4*)(Vs + r * 128 + d4) = *(const float4*)(Vt + (size_t)r * HD_ + d4);
        }
        __syncthreads();

        float sacc[4][4];
#pragma unroll
        for (int i = 0; i < 4; i++)
#pragma unroll
            for (int j = 0; j < 4; j++) sacc[i][j] = 0.0f;

#pragma unroll 4
        for (int d = 0; d < 128; d++) {
            float4 qv = *(const float4*)(Qs + d * 64 + ty * 4);
            float4 kv = *(const float4*)(Ks + d * 64 + tx * 4);
            float qa[4] = {qv.x, qv.y, qv.z, qv.w};
            float ka[4] = {kv.x, kv.y, kv.z, kv.w};
#pragma unroll
            for (int i = 0; i < 4; i++)
#pragma unroll
                for (int j = 0; j < 4; j++)
                    sacc[i][j] += qa[i] * ka[j];
        }

#pragma unroll
        for (int i = 0; i < 4; i++)
#pragma unroll
            for (int j = 0; j < 4; j++) sacc[i][j] *= SCALE_;

        if (j0 == q0) {
#pragma unroll
            for (int i = 0; i < 4; i++)
#pragma unroll
                for (int j = 0; j < 4; j++)
                    if (tx * 4 + j > ty * 4 + i) sacc[i][j] = -1e30f;
        }

#pragma unroll
        for (int i = 0; i < 4; i++) {
            float rm = fmaxf(fmaxf(sacc[i][0], sacc[i][1]),
                             fmaxf(sacc[i][2], sacc[i][3]));
#pragma unroll
            for (int off = 8; off >= 1; off >>= 1)
                rm = fmaxf(rm, __shfl_xor_sync(0xffffffffu, rm, off));
            float mn   = fmaxf(m[i], rm);
            float corr = __expf(m[i] - mn);
            float p0 = __expf(sacc[i][0] - mn);
            float p1 = __expf(sacc[i][1] - mn);
            float p2 = __expf(sacc[i][2] - mn);
            float p3 = __expf(sacc[i][3] - mn);
            float rs = p0 + p1 + p2 + p3;
#pragma unroll
            for (int off = 8; off >= 1; off >>= 1)
                rs += __shfl_xor_sync(0xffffffffu, rs, off);
            l[i] = l[i] * corr + rs;
            m[i] = mn;
#pragma unroll
            for (int j = 0; j < 8; j++) o[i][j] *= corr;
            *(float4*)(Ps + (ty * 4 + i) * 64 + tx * 4) = make_float4(p0, p1, p2, p3);
        }
        __syncthreads();

#pragma unroll 2
        for (int jj = 0; jj < 64; jj++) {
            float pr[4];
#pragma unroll
            for (int i = 0; i < 4; i++) pr[i] = Ps[(ty * 4 + i) * 64 + jj];
            float4 v0 = *(const float4*)(Vs + jj * 128 + tx * 8);
            float4 v1 = *(const float4*)(Vs + jj * 128 + tx * 8 + 4);
            float va[8] = {v0.x, v0.y, v0.z, v0.w, v1.x, v1.y, v1.z, v1.w};
#pragma unroll
            for (int i = 0; i < 4; i++)
#pragma unroll
                for (int j = 0; j < 8; j++)
                    o[i][j] += pr[i] * va[j];
        }
    }

    // epilogue: normalize, round to tf32 (feeds O-proj GEMM), write [B,S,H*HD]
#pragma unroll
    for (int i = 0; i < 4; i++) {
        float inv = 1.0f / l[i];
        int r = q0 * 64 + ty * 4 + i;
        float* dst = g_attn + ((size_t)(b * S_ + r) * H_ + h) * HD_ + tx * 8;
        *(float4*)(dst + 0) = make_float4(to_tf32(o[i][0] * inv), to_tf32(o[i][1] * inv),
                                          to_tf32(o[i][2] * inv), to_tf32(o[i][3] * inv));
        *(float4*)(dst + 4) = make_float4(to_tf32(o[i][4] * inv), to_tf32(o[i][5] * inv),
                                          to_tf32(o[i][6] * inv), to_tf32(o[i][7] * inv));
    }
}

// ---------------- host launcher ----------------
extern "C" void kernel_launch(void* const* d_in, const int* in_sizes, int n_in,
                              void* d_out, int out_size) {
    const int*   positions = (const int*)  d_in[0];
    const float* hidden    = (const float*)d_in[1];
    const float* w_qkv     = (const float*)d_in[2];
    const float* w_o       = (const float*)d_in[3];
    const float* q_norm_w  = (const float*)d_in[4];
    const float* k_norm_w  = (const float*)d_in[5];
    float*       out       = (float*)d_out;

    float *qkv_ptr, *attn_ptr, *hid_ptr, *wqkv_ptr, *wo_ptr;
    cudaGetSymbolAddress((void**)&qkv_ptr,  g_qkv);
    cudaGetSymbolAddress((void**)&attn_ptr, g_attn);
    cudaGetSymbolAddress((void**)&hid_ptr,  g_hidden);
    cudaGetSymbolAddress((void**)&wqkv_ptr, g_wqkv);
    cudaGetSymbolAddress((void**)&wo_ptr,   g_wo);

    cudaFuncSetAttribute(attention_kernel,
                         cudaFuncAttributeMaxDynamicSharedMemorySize, ATT_SMEM_BYTES);
    cudaFuncSetAttribute(gemm_tf32_db_kernel,
                         cudaFuncAttributeMaxDynamicSharedMemorySize, GEMM_SMEM_BYTES);

    // 0) pre-round GEMM operands to tf32 (once, not per-tile)
    cvt_tf32_kernel<<<(T_ * D_) / 1024, 256>>>(hidden, hid_ptr, T_ * D_);
    cvt_tf32_kernel<<<(D_ * NQKV_) / 1024, 256>>>(w_qkv, wqkv_ptr, D_ * NQKV_);
    cvt_tf32_kernel<<<(H_ * HD_ * D_) / 1024, 256>>>(w_o, wo_ptr, H_ * HD_ * D_);

    // 1) RoPE tables
    rope_table_kernel<<<(S_ * 64 + 255) / 256, 256>>>();

    // 2) QKV projection: [4096,4096] @ [4096,6144]  (tf32, cp.async double-buffered)
    gemm_tf32_db_kernel<<<dim3(NQKV_ / 128, T_ / 128), 256, GEMM_SMEM_BYTES>>>(
        hid_ptr, wqkv_ptr, qkv_ptr, T_, NQKV_, D_);

    // 3) RMSNorm + RoPE + layout
    normrope_kernel<<<T_, 256>>>(q_norm_w, k_norm_w, positions);

    // 4) causal GQA flash attention
    attention_kernel<<<dim3(S_ / 64, H_, B_), 256, ATT_SMEM_BYTES>>>();

    // 5) output projection: [4096,4096] @ [4096,4096] -> d_out
    gemm_tf32_db_kernel<<<dim3(D_ / 128, T_ / 128), 256, GEMM_SMEM_BYTES>>>(
        attn_ptr, wo_ptr, out, T_, D_, H_ * HD_);
}